// round 6
// baseline (speedup 1.0000x reference)
#include <cuda_runtime.h>
#include <cstdint>

// ---------------------------------------------------------------------------
// y[b,i,t,e] = sum_{j,d} x[b,j,t,d] * sign[i,j]*W[widx[i,j]][d,e]*beta[e]
// == per-b GEMM: Y[4096 x 1024] = X[4096 x 1024(k=j,d)] @ WfT^T,
//    WfT[n=(i,e)][k=(j,d)] row-major (B operand).
//
// sm_100 (non-'a'): legacy mma.sync tf32. Fragments loaded with ldmatrix.x4
// (tf32 tile viewed as b16): 6 wide loads per warp per k-step instead of 20
// scalar/64b LDS. Padded smem stride 36 floats -> conflict-free ldmatrix.
// ---------------------------------------------------------------------------

constexpr int NS = 3;                   // pipeline stages
constexpr int LDR = 36;                 // smem row stride (floats), A and B
constexpr int A_FLOATS = 128 * LDR;     // 4608
constexpr int STAGE_FLOATS = 2 * A_FLOATS;          // A tile + B tile
constexpr int SMEM_BYTES = NS * STAGE_FLOATS * 4;   // 110592 -> 2 CTAs/SM
constexpr int STAGE_BYTES = STAGE_FLOATS * 4;
constexpr int B_OFF_BYTES = A_FLOATS * 4;           // B tile offset in stage

// Fused weight, transposed: WfT[n=(i,e)][k=(j,d)], tf32-rounded,
// beta + sign + A-truncation compensation folded in.
__device__ float g_WfT[1024 * 1024];

__constant__ float c_sign[64] = {
 +1,-1,-1,-1,-1,-1,-1,-1,
 +1,+1,+1,-1,+1,-1,-1,+1,
 +1,-1,+1,+1,+1,+1,-1,-1,
 +1,+1,-1,+1,+1,-1,+1,-1,
 +1,-1,-1,-1,+1,+1,+1,+1,
 +1,+1,-1,+1,-1,+1,-1,+1,
 +1,+1,+1,-1,-1,+1,+1,-1,
 +1,-1,+1,+1,-1,-1,+1,+1};
__constant__ int c_widx[64] = {
 0,1,2,3,4,5,6,7,
 1,0,3,2,5,4,7,6,
 2,3,0,1,6,7,4,5,
 3,2,1,0,7,6,5,4,
 4,5,6,7,0,1,2,3,
 5,4,7,6,1,0,3,2,
 6,7,4,5,2,3,0,1,
 7,6,5,4,3,2,1,0};

// Compensation for tf32 RZ-truncation of the A operand inside the tensor core:
// mean relative loss = 2^-11 * E[1/m], m log-uniform in [1,2) -> 3.52e-4.
#define A_TRUNC_COMP 1.000352f

// ---------------- PTX helpers ----------------
__device__ __forceinline__ void cp_async16(uint32_t dst, const void* src) {
    asm volatile("cp.async.cg.shared.global [%0], [%1], 16;\n"
                 :: "r"(dst), "l"(src) : "memory");
}
__device__ __forceinline__ void cp_commit() {
    asm volatile("cp.async.commit_group;\n" ::: "memory");
}
template <int N>
__device__ __forceinline__ void cp_wait() {
    asm volatile("cp.async.wait_group %0;\n" :: "n"(N) : "memory");
}
__device__ __forceinline__ uint32_t smem_u32(const void* p) {
    uint32_t a;
    asm("{ .reg .u64 t; cvta.to.shared.u64 t, %1; cvt.u32.u64 %0, t; }"
        : "=r"(a) : "l"(p));
    return a;
}
__device__ __forceinline__ void ldsm_x4(uint32_t* r, uint32_t addr) {
    asm volatile("ldmatrix.sync.aligned.m8n8.x4.shared.b16 {%0,%1,%2,%3}, [%4];"
                 : "=r"(r[0]), "=r"(r[1]), "=r"(r[2]), "=r"(r[3]) : "r"(addr));
}

// ---------------- Wf prep (transposed, coalesced both sides) ----------------
__global__ void prep_wf_kernel(const float* __restrict__ W,
                               const float* __restrict__ beta) {
    __shared__ float s[32][33];
    const int kb = blockIdx.x * 32;   // k tile
    const int nb = blockIdx.y * 32;   // n tile
    const int i = nb >> 7, j = kb >> 7;
    const float sg = c_sign[i * 8 + j] * A_TRUNC_COMP;
    const int w = c_widx[i * 8 + j];
    const int e0 = nb & 127, d0 = kb & 127;
    s[threadIdx.y][threadIdx.x] =
        W[(w << 14) + (d0 + threadIdx.y) * 128 + (e0 + threadIdx.x)];
    __syncthreads();
    float v = s[threadIdx.x][threadIdx.y] * sg * beta[e0 + threadIdx.y];
    uint32_t t;
    asm("cvt.rna.tf32.f32 %0, %1;" : "=r"(t) : "f"(v));
    g_WfT[(size_t)(nb + threadIdx.y) * 1024 + kb + threadIdx.x] =
        __uint_as_float(t);
}

// ---------------- main GEMM ----------------
__global__ __launch_bounds__(256, 2)
void octo_gemm_kernel(const float* __restrict__ x, float* __restrict__ y) {
    extern __shared__ float sm[];
    const uint32_t sbase = smem_u32(sm);
    const int tid = threadIdx.x;
    const int lane = tid & 31;
    const int warp = tid >> 5;
    const int warp_m = warp & 1;   // 2 warps over M (64 rows each)
    const int warp_n = warp >> 1;  // 4 warps over N (32 cols each)

    const int nb = blockIdx.x;         // 0..7 -> head i, n0 = nb*128
    const int t0 = blockIdx.y * 128;   // t tile
    const int b  = blockIdx.z;

    // cp.async thread mapping: 32 rows x 8 chunks of 16B per pass
    const int cr = tid >> 3;
    const int cc = tid & 7;

    const float* xb = x + (size_t)b * (8u * 4096u * 128u);
    const float* gB = g_WfT + ((size_t)nb * 128) * 1024;

    auto issue_stage = [&](int kc) {
        const int s = kc % NS;
        const uint32_t a_base = sbase + (uint32_t)(s * STAGE_BYTES);
        const uint32_t b_base = a_base + B_OFF_BYTES;
        const int j = kc >> 2;
        const int d0 = (kc & 3) * 32;
        const float* srcA = xb + ((size_t)j * 4096 + t0) * 128 + d0;
        const float* srcB = gB + kc * 32;
        #pragma unroll
        for (int it = 0; it < 4; it++) {          // A: 128 rows x 32 floats
            const int r = cr + 32 * it;
            cp_async16(a_base + (uint32_t)(r * LDR + cc * 4) * 4u,
                       srcA + (size_t)r * 128 + cc * 4);
        }
        #pragma unroll
        for (int it = 0; it < 4; it++) {          // B: 128 n-rows x 32 floats
            const int r = cr + 32 * it;
            cp_async16(b_base + (uint32_t)(r * LDR + cc * 4) * 4u,
                       srcB + (size_t)r * 1024 + cc * 4);
        }
    };

    issue_stage(0); cp_commit();
    issue_stage(1); cp_commit();

    float acc[4][4][4];
    #pragma unroll
    for (int mt = 0; mt < 4; mt++)
        #pragma unroll
        for (int nt = 0; nt < 4; nt++)
            #pragma unroll
            for (int c = 0; c < 4; c++) acc[mt][nt][c] = 0.0f;

    // ldmatrix per-thread base addresses (byte offsets within a stage)
    // A: tile rows mt*16 + rowadj + (lane&7), col floats ks*8 + coladj
    const uint32_t a_row = (uint32_t)(warp_m * 64 + ((lane >> 3) & 1) * 8 + (lane & 7));
    const uint32_t a_off0 = (a_row * LDR + ((lane >> 4) & 1) * 4) * 4u;
    // B: tile rows warp_n*32 + pr*16 + ntadj + (lane&7), col floats ks*8 + kadj
    const uint32_t b_row = (uint32_t)(warp_n * 32 + ((lane >> 4) & 1) * 8 + (lane & 7));
    const uint32_t b_off0 = (uint32_t)B_OFF_BYTES +
                            (b_row * LDR + ((lane >> 3) & 1) * 4) * 4u;

    uint32_t aF[2][4][4];   // [buf][mt][reg]
    uint32_t bF[2][2][4];   // [buf][pr][reg]  (pr covers nt {2pr, 2pr+1})

    for (int kc = 0; kc < 32; kc++) {
        cp_wait<NS - 2>();
        __syncthreads();
        if (kc + 2 < 32) issue_stage(kc + 2);
        cp_commit();                      // empty tail groups keep counts uniform

        const uint32_t stg = sbase + (uint32_t)((kc % NS) * STAGE_BYTES);
        const uint32_t aS = stg + a_off0;
        const uint32_t bS = stg + b_off0;

        // prefetch ks=0 fragments
        #pragma unroll
        for (int mt = 0; mt < 4; mt++) ldsm_x4(aF[0][mt], aS + mt * (16 * LDR * 4));
        #pragma unroll
        for (int pr = 0; pr < 2; pr++)  ldsm_x4(bF[0][pr], bS + pr * (16 * LDR * 4));

        #pragma unroll
        for (int ks = 0; ks < 4; ks++) {
            const int cur = ks & 1, nxt = cur ^ 1;
            if (ks < 3) {   // prefetch ks+1 before the MMAs of ks
                const uint32_t aS1 = aS + (ks + 1) * 32;
                const uint32_t bS1 = bS + (ks + 1) * 32;
                #pragma unroll
                for (int mt = 0; mt < 4; mt++)
                    ldsm_x4(aF[nxt][mt], aS1 + mt * (16 * LDR * 4));
                #pragma unroll
                for (int pr = 0; pr < 2; pr++)
                    ldsm_x4(bF[nxt][pr], bS1 + pr * (16 * LDR * 4));
            }
            #pragma unroll
            for (int mt = 0; mt < 4; mt++)
                #pragma unroll
                for (int nt = 0; nt < 4; nt++) {
                    const uint32_t* bp = &bF[cur][nt >> 1][(nt & 1) * 2];
                    asm volatile(
                        "mma.sync.aligned.m16n8k8.row.col.f32.tf32.tf32.f32 "
                        "{%0,%1,%2,%3}, {%4,%5,%6,%7}, {%8,%9}, {%0,%1,%2,%3};\n"
                        : "+f"(acc[mt][nt][0]), "+f"(acc[mt][nt][1]),
                          "+f"(acc[mt][nt][2]), "+f"(acc[mt][nt][3])
                        : "r"(aF[cur][mt][0]), "r"(aF[cur][mt][1]),
                          "r"(aF[cur][mt][2]), "r"(aF[cur][mt][3]),
                          "r"(bp[0]), "r"(bp[1]));
                }
        }
    }

    // epilogue: y[b][i=nb][t][e]
    float* yb = y + ((size_t)b * 8 + nb) * 4096u * 128u;
    #pragma unroll
    for (int mt = 0; mt < 4; mt++) {
        const int row = t0 + warp_m * 64 + mt * 16 + (lane >> 2);
        #pragma unroll
        for (int nt = 0; nt < 4; nt++) {
            const int e = warp_n * 32 + nt * 8 + (lane & 3) * 2;
            *reinterpret_cast<float2*>(yb + (size_t)row * 128 + e) =
                make_float2(acc[mt][nt][0], acc[mt][nt][1]);
            *reinterpret_cast<float2*>(yb + (size_t)(row + 8) * 128 + e) =
                make_float2(acc[mt][nt][2], acc[mt][nt][3]);
        }
    }
}

extern "C" void kernel_launch(void* const* d_in, const int* in_sizes, int n_in,
                              void* d_out, int out_size) {
    const float* x    = (const float*)d_in[0];   // [8,8,4096,128] fp32
    const float* W    = (const float*)d_in[1];   // [8,128,128] fp32
    const float* beta = (const float*)d_in[2];   // [128] fp32
    float* y = (float*)d_out;                    // [8,8,4096,128] fp32
    (void)in_sizes; (void)n_in; (void)out_size;

    cudaFuncSetAttribute(octo_gemm_kernel,
                         cudaFuncAttributeMaxDynamicSharedMemorySize, SMEM_BYTES);

    prep_wf_kernel<<<dim3(32, 32), dim3(32, 32)>>>(W, beta);

    dim3 grid(8, 32, 8);   // n-tiles fastest: 8 CTAs share each x tile in L2
    octo_gemm_kernel<<<grid, 256, SMEM_BYTES>>>(x, y);
}

// round 7
// speedup vs baseline: 1.6262x; 1.6262x over previous
#include <cuda_runtime.h>
#include <cuda_fp16.h>
#include <cstdint>

// ---------------------------------------------------------------------------
// y[b,i,t,e] = sum_{j,d} x[b,j,t,d] * sign[i,j]*W[widx[i,j]][d,e]*beta[e]
// == per-b GEMM: Y[4096 x 1024] = X[4096 x 1024(k=j,d)] @ WfT^T,
//    WfT[n=(i,e)][k=(j,d)] row-major (B operand).
//
// sm_100 legacy mma.sync path. fp16 (11-bit mantissa == tf32) with
// m16n8k16 halves the MMA instruction count vs tf32 m16n8k8 at equal
// precision. x pre-converted to fp16 once (DRAM is ~6x under-utilized).
// ---------------------------------------------------------------------------

constexpr int NS = 3;                    // pipeline stages
constexpr int LDH = 72;                  // smem row stride in fp16 (64 + 8 pad)
constexpr int TILE_H_BYTES = 128 * LDH * 2;          // 18432 per operand tile
constexpr int STAGE_BYTES = 2 * TILE_H_BYTES;        // 36864
constexpr int SMEM_BYTES = NS * STAGE_BYTES;         // 110592 -> 2 CTAs/SM
constexpr int B_OFF_BYTES = TILE_H_BYTES;

// x converted to fp16, same [b][j][t][d] layout (67 MB scratch).
__device__ __half g_xh[8u * 8u * 4096u * 128u];
// Fused weight, transposed, fp16: WfT[n=(i,e)][k=(j,d)], beta+sign folded in.
__device__ __half g_WfT[1024 * 1024];

__constant__ float c_sign[64] = {
 +1,-1,-1,-1,-1,-1,-1,-1,
 +1,+1,+1,-1,+1,-1,-1,+1,
 +1,-1,+1,+1,+1,+1,-1,-1,
 +1,+1,-1,+1,+1,-1,+1,-1,
 +1,-1,-1,-1,+1,+1,+1,+1,
 +1,+1,-1,+1,-1,+1,-1,+1,
 +1,+1,+1,-1,-1,+1,+1,-1,
 +1,-1,+1,+1,-1,-1,+1,+1};
__constant__ int c_widx[64] = {
 0,1,2,3,4,5,6,7,
 1,0,3,2,5,4,7,6,
 2,3,0,1,6,7,4,5,
 3,2,1,0,7,6,5,4,
 4,5,6,7,0,1,2,3,
 5,4,7,6,1,0,3,2,
 6,7,4,5,2,3,0,1,
 7,6,5,4,3,2,1,0};

// ---------------- PTX helpers ----------------
__device__ __forceinline__ void cp_async16(uint32_t dst, const void* src) {
    asm volatile("cp.async.cg.shared.global [%0], [%1], 16;\n"
                 :: "r"(dst), "l"(src) : "memory");
}
__device__ __forceinline__ void cp_commit() {
    asm volatile("cp.async.commit_group;\n" ::: "memory");
}
template <int N>
__device__ __forceinline__ void cp_wait() {
    asm volatile("cp.async.wait_group %0;\n" :: "n"(N) : "memory");
}
__device__ __forceinline__ uint32_t smem_u32(const void* p) {
    uint32_t a;
    asm("{ .reg .u64 t; cvta.to.shared.u64 t, %1; cvt.u32.u64 %0, t; }"
        : "=r"(a) : "l"(p));
    return a;
}
__device__ __forceinline__ void ldsm_x4(uint32_t* r, uint32_t addr) {
    asm volatile("ldmatrix.sync.aligned.m8n8.x4.shared.b16 {%0,%1,%2,%3}, [%4];"
                 : "=r"(r[0]), "=r"(r[1]), "=r"(r[2]), "=r"(r[3]) : "r"(addr));
}

// ---------------- x fp32 -> fp16 conversion ----------------
__global__ void conv_x_kernel(const float* __restrict__ x) {
    const size_t i = (size_t)blockIdx.x * 256 + threadIdx.x;   // 8.39M threads
    const float4 v = reinterpret_cast<const float4*>(x)[i];
    __half2* out = reinterpret_cast<__half2*>(g_xh);
    out[2 * i + 0] = __floats2half2_rn(v.x, v.y);
    out[2 * i + 1] = __floats2half2_rn(v.z, v.w);
}

// ---------------- Wf prep (transposed, fp16) ----------------
__global__ void prep_wf_kernel(const float* __restrict__ W,
                               const float* __restrict__ beta) {
    __shared__ float s[32][33];
    const int kb = blockIdx.x * 32;   // k tile
    const int nb = blockIdx.y * 32;   // n tile
    const int i = nb >> 7, j = kb >> 7;
    const float sg = c_sign[i * 8 + j];
    const int w = c_widx[i * 8 + j];
    const int e0 = nb & 127, d0 = kb & 127;
    s[threadIdx.y][threadIdx.x] =
        W[(w << 14) + (d0 + threadIdx.y) * 128 + (e0 + threadIdx.x)];
    __syncthreads();
    const float v = s[threadIdx.x][threadIdx.y] * sg * beta[e0 + threadIdx.y];
    g_WfT[(size_t)(nb + threadIdx.y) * 1024 + kb + threadIdx.x] =
        __float2half_rn(v);
}

// ---------------- main GEMM (fp16 m16n8k16) ----------------
__global__ __launch_bounds__(256, 2)
void octo_gemm_kernel(float* __restrict__ y) {
    extern __shared__ __align__(128) char smc[];
    const uint32_t sbase = smem_u32(smc);
    const int tid = threadIdx.x;
    const int lane = tid & 31;
    const int warp = tid >> 5;
    const int warp_m = warp & 1;   // 2 warps over M (64 rows each)
    const int warp_n = warp >> 1;  // 4 warps over N (32 cols each)

    const int nb = blockIdx.x;         // 0..7 -> head i
    const int t0 = blockIdx.y * 128;   // t tile
    const int b  = blockIdx.z;

    // cp.async mapping: 128 rows x 8 chunks(16B = 8 fp16); 1024 chunks/tile
    const int cr = tid >> 3;           // row 0..31 per pass
    const int cc = tid & 7;            // chunk in row

    const __half* xb = g_xh + (size_t)b * (8u * 4096u * 128u);
    const __half* gB = g_WfT + ((size_t)nb * 128) * 1024;

    auto issue_stage = [&](int kc) {   // kc 0..15, K-chunk = 64 fp16
        const int s = kc % NS;
        const uint32_t a_base = sbase + (uint32_t)(s * STAGE_BYTES);
        const uint32_t b_base = a_base + B_OFF_BYTES;
        const int j = kc >> 1;
        const int d0 = (kc & 1) * 64;
        const __half* srcA = xb + ((size_t)j * 4096 + t0) * 128 + d0;
        const __half* srcB = gB + kc * 64;
        #pragma unroll
        for (int it = 0; it < 4; it++) {
            const int r = cr + 32 * it;
            cp_async16(a_base + (uint32_t)(r * LDH + cc * 8) * 2u,
                       srcA + (size_t)r * 128 + cc * 8);
            cp_async16(b_base + (uint32_t)(r * LDH + cc * 8) * 2u,
                       srcB + (size_t)r * 1024 + cc * 8);
        }
    };

    issue_stage(0); cp_commit();
    issue_stage(1); cp_commit();

    float acc[4][4][4];
    #pragma unroll
    for (int mt = 0; mt < 4; mt++)
        #pragma unroll
        for (int nt = 0; nt < 4; nt++)
            #pragma unroll
            for (int c = 0; c < 4; c++) acc[mt][nt][c] = 0.0f;

    // ldmatrix lane addressing (byte offsets within a stage)
    // A (16x16 tile per mt): oct0 rows0-7/k0-7, oct1 rows8-15/k0-7,
    //                        oct2 rows0-7/k8-15, oct3 rows8-15/k8-15
    const uint32_t a_row = (uint32_t)(warp_m * 64 + ((lane >> 3) & 1) * 8 + (lane & 7));
    const uint32_t a_off0 = (a_row * LDH + ((lane >> 4) & 1) * 8) * 2u;
    // B (16n x 16k per pr): oct0 n0-7/k0-7, oct1 n0-7/k8-15,
    //                       oct2 n8-15/k0-7, oct3 n8-15/k8-15
    const uint32_t b_row = (uint32_t)(warp_n * 32 + ((lane >> 4) & 1) * 8 + (lane & 7));
    const uint32_t b_off0 = (uint32_t)B_OFF_BYTES +
                            (b_row * LDH + ((lane >> 3) & 1) * 8) * 2u;

    uint32_t aF[2][4][4];   // [buf][mt][reg]
    uint32_t bF[2][2][4];   // [buf][pr][reg]: {b0,b1} of nt=2pr, then nt=2pr+1

    for (int kc = 0; kc < 16; kc++) {
        cp_wait<NS - 2>();
        __syncthreads();
        if (kc + 2 < 16) issue_stage(kc + 2);
        cp_commit();                      // empty tail groups keep counts uniform

        const uint32_t stg = sbase + (uint32_t)((kc % NS) * STAGE_BYTES);
        const uint32_t aS = stg + a_off0;
        const uint32_t bS = stg + b_off0;

        // prefetch ks=0 fragments
        #pragma unroll
        for (int mt = 0; mt < 4; mt++) ldsm_x4(aF[0][mt], aS + mt * (16 * LDH * 2));
        #pragma unroll
        for (int pr = 0; pr < 2; pr++)  ldsm_x4(bF[0][pr], bS + pr * (16 * LDH * 2));

        #pragma unroll
        for (int ks = 0; ks < 4; ks++) {   // K = 16 fp16 per ks
            const int cur = ks & 1, nxt = cur ^ 1;
            if (ks < 3) {   // prefetch ks+1 before the MMAs of ks
                const uint32_t aS1 = aS + (ks + 1) * 32;   // 16 fp16 = 32 B
                const uint32_t bS1 = bS + (ks + 1) * 32;
                #pragma unroll
                for (int mt = 0; mt < 4; mt++)
                    ldsm_x4(aF[nxt][mt], aS1 + mt * (16 * LDH * 2));
                #pragma unroll
                for (int pr = 0; pr < 2; pr++)
                    ldsm_x4(bF[nxt][pr], bS1 + pr * (16 * LDH * 2));
            }
            #pragma unroll
            for (int mt = 0; mt < 4; mt++)
                #pragma unroll
                for (int nt = 0; nt < 4; nt++) {
                    const uint32_t* bp = &bF[cur][nt >> 1][(nt & 1) * 2];
                    asm volatile(
                        "mma.sync.aligned.m16n8k16.row.col.f32.f16.f16.f32 "
                        "{%0,%1,%2,%3}, {%4,%5,%6,%7}, {%8,%9}, {%0,%1,%2,%3};\n"
                        : "+f"(acc[mt][nt][0]), "+f"(acc[mt][nt][1]),
                          "+f"(acc[mt][nt][2]), "+f"(acc[mt][nt][3])
                        : "r"(aF[cur][mt][0]), "r"(aF[cur][mt][1]),
                          "r"(aF[cur][mt][2]), "r"(aF[cur][mt][3]),
                          "r"(bp[0]), "r"(bp[1]));
                }
        }
    }

    // epilogue: y[b][i=nb][t][e]
    float* yb = y + ((size_t)b * 8 + nb) * 4096u * 128u;
    #pragma unroll
    for (int mt = 0; mt < 4; mt++) {
        const int row = t0 + warp_m * 64 + mt * 16 + (lane >> 2);
        #pragma unroll
        for (int nt = 0; nt < 4; nt++) {
            const int e = warp_n * 32 + nt * 8 + (lane & 3) * 2;
            *reinterpret_cast<float2*>(yb + (size_t)row * 128 + e) =
                make_float2(acc[mt][nt][0], acc[mt][nt][1]);
            *reinterpret_cast<float2*>(yb + (size_t)(row + 8) * 128 + e) =
                make_float2(acc[mt][nt][2], acc[mt][nt][3]);
        }
    }
}

extern "C" void kernel_launch(void* const* d_in, const int* in_sizes, int n_in,
                              void* d_out, int out_size) {
    const float* x    = (const float*)d_in[0];   // [8,8,4096,128] fp32
    const float* W    = (const float*)d_in[1];   // [8,128,128] fp32
    const float* beta = (const float*)d_in[2];   // [128] fp32
    float* y = (float*)d_out;                    // [8,8,4096,128] fp32
    (void)in_sizes; (void)n_in; (void)out_size;

    cudaFuncSetAttribute(octo_gemm_kernel,
                         cudaFuncAttributeMaxDynamicSharedMemorySize, SMEM_BYTES);

    conv_x_kernel<<<32768, 256>>>(x);                    // 33.5M elems / 4 per thread
    prep_wf_kernel<<<dim3(32, 32), dim3(32, 32)>>>(W, beta);

    dim3 grid(8, 32, 8);   // n-tiles fastest: 8 CTAs share each x tile in L2
    octo_gemm_kernel<<<grid, 256, SMEM_BYTES>>>(y);
}

// round 8
// speedup vs baseline: 1.7940x; 1.1032x over previous
#include <cuda_runtime.h>
#include <cuda_fp16.h>
#include <cstdint>

// ---------------------------------------------------------------------------
// y[b,i,t,e] = sum_{j,d} x[b,j,t,d] * sign[i,j]*W[widx[i,j]][d,e]*beta[e]
// == per-b GEMM: Y[4096 x 1024] = X[4096 x 1024(k=j,d)] @ WfT^T,
//    WfT[n=(i,e)][k=(j,d)] row-major (B operand).
//
// fp16 m16n8k16 legacy mma.sync (11-bit mantissa == tf32 precision).
// This round: fragments software-pipelined ACROSS kc boundaries — the
// cp_wait + __syncthreads + next-stage ldmatrix happen before the last
// k-step's MMAs, hiding the per-chunk sync window behind tensor work.
// ---------------------------------------------------------------------------

constexpr int NS = 3;                    // pipeline stages
constexpr int LDH = 72;                  // smem row stride in fp16 (64 + 8 pad)
constexpr int TILE_H_BYTES = 128 * LDH * 2;          // 18432 per operand tile
constexpr int STAGE_BYTES = 2 * TILE_H_BYTES;        // 36864
constexpr int SMEM_BYTES = NS * STAGE_BYTES;         // 110592 -> 2 CTAs/SM
constexpr int B_OFF_BYTES = TILE_H_BYTES;

// x converted to fp16, same [b][j][t][d] layout (67 MB scratch).
__device__ __half g_xh[8u * 8u * 4096u * 128u];
// Fused weight, transposed, fp16: WfT[n=(i,e)][k=(j,d)], beta+sign folded in.
__device__ __half g_WfT[1024 * 1024];

__constant__ float c_sign[64] = {
 +1,-1,-1,-1,-1,-1,-1,-1,
 +1,+1,+1,-1,+1,-1,-1,+1,
 +1,-1,+1,+1,+1,+1,-1,-1,
 +1,+1,-1,+1,+1,-1,+1,-1,
 +1,-1,-1,-1,+1,+1,+1,+1,
 +1,+1,-1,+1,-1,+1,-1,+1,
 +1,+1,+1,-1,-1,+1,+1,-1,
 +1,-1,+1,+1,-1,-1,+1,+1};
__constant__ int c_widx[64] = {
 0,1,2,3,4,5,6,7,
 1,0,3,2,5,4,7,6,
 2,3,0,1,6,7,4,5,
 3,2,1,0,7,6,5,4,
 4,5,6,7,0,1,2,3,
 5,4,7,6,1,0,3,2,
 6,7,4,5,2,3,0,1,
 7,6,5,4,3,2,1,0};

// ---------------- PTX helpers ----------------
__device__ __forceinline__ void cp_async16(uint32_t dst, const void* src) {
    asm volatile("cp.async.cg.shared.global [%0], [%1], 16;\n"
                 :: "r"(dst), "l"(src) : "memory");
}
__device__ __forceinline__ void cp_commit() {
    asm volatile("cp.async.commit_group;\n" ::: "memory");
}
template <int N>
__device__ __forceinline__ void cp_wait() {
    asm volatile("cp.async.wait_group %0;\n" :: "n"(N) : "memory");
}
__device__ __forceinline__ uint32_t smem_u32(const void* p) {
    uint32_t a;
    asm("{ .reg .u64 t; cvta.to.shared.u64 t, %1; cvt.u32.u64 %0, t; }"
        : "=r"(a) : "l"(p));
    return a;
}
__device__ __forceinline__ void ldsm_x4(uint32_t* r, uint32_t addr) {
    asm volatile("ldmatrix.sync.aligned.m8n8.x4.shared.b16 {%0,%1,%2,%3}, [%4];"
                 : "=r"(r[0]), "=r"(r[1]), "=r"(r[2]), "=r"(r[3]) : "r"(addr));
}

// ---------------- x fp32 -> fp16 conversion ----------------
__global__ void conv_x_kernel(const float* __restrict__ x) {
    const size_t i = (size_t)blockIdx.x * 256 + threadIdx.x;   // 8.39M threads
    const float4 v = reinterpret_cast<const float4*>(x)[i];
    __half2* out = reinterpret_cast<__half2*>(g_xh);
    out[2 * i + 0] = __floats2half2_rn(v.x, v.y);
    out[2 * i + 1] = __floats2half2_rn(v.z, v.w);
}

// ---------------- Wf prep (transposed, fp16) ----------------
__global__ void prep_wf_kernel(const float* __restrict__ W,
                               const float* __restrict__ beta) {
    __shared__ float s[32][33];
    const int kb = blockIdx.x * 32;   // k tile
    const int nb = blockIdx.y * 32;   // n tile
    const int i = nb >> 7, j = kb >> 7;
    const float sg = c_sign[i * 8 + j];
    const int w = c_widx[i * 8 + j];
    const int e0 = nb & 127, d0 = kb & 127;
    s[threadIdx.y][threadIdx.x] =
        W[(w << 14) + (d0 + threadIdx.y) * 128 + (e0 + threadIdx.x)];
    __syncthreads();
    const float v = s[threadIdx.x][threadIdx.y] * sg * beta[e0 + threadIdx.y];
    g_WfT[(size_t)(nb + threadIdx.y) * 1024 + kb + threadIdx.x] =
        __float2half_rn(v);
}

// ---------------- main GEMM (fp16 m16n8k16, cross-kc pipelined) ----------------
__global__ __launch_bounds__(256, 2)
void octo_gemm_kernel(float* __restrict__ y) {
    extern __shared__ __align__(128) char smc[];
    const uint32_t sbase = smem_u32(smc);
    const int tid = threadIdx.x;
    const int lane = tid & 31;
    const int warp = tid >> 5;
    const int warp_m = warp & 1;   // 2 warps over M (64 rows each)
    const int warp_n = warp >> 1;  // 4 warps over N (32 cols each)

    const int nb = blockIdx.x;         // 0..7 -> head i
    const int t0 = blockIdx.y * 128;   // t tile
    const int b  = blockIdx.z;

    // cp.async mapping: 128 rows x 8 chunks(16B = 8 fp16)
    const int cr = tid >> 3;
    const int cc = tid & 7;

    const __half* xb = g_xh + (size_t)b * (8u * 4096u * 128u);
    const __half* gB = g_WfT + ((size_t)nb * 128) * 1024;

    auto issue_stage = [&](int kc) {   // kc 0..15, K-chunk = 64 fp16
        const int s = kc % NS;
        const uint32_t a_base = sbase + (uint32_t)(s * STAGE_BYTES);
        const uint32_t b_base = a_base + B_OFF_BYTES;
        const int j = kc >> 1;
        const int d0 = (kc & 1) * 64;
        const __half* srcA = xb + ((size_t)j * 4096 + t0) * 128 + d0;
        const __half* srcB = gB + kc * 64;
        #pragma unroll
        for (int it = 0; it < 4; it++) {
            const int r = cr + 32 * it;
            cp_async16(a_base + (uint32_t)(r * LDH + cc * 8) * 2u,
                       srcA + (size_t)r * 128 + cc * 8);
            cp_async16(b_base + (uint32_t)(r * LDH + cc * 8) * 2u,
                       srcB + (size_t)r * 1024 + cc * 8);
        }
    };

    float acc[4][4][4];
    #pragma unroll
    for (int mt = 0; mt < 4; mt++)
        #pragma unroll
        for (int nt = 0; nt < 4; nt++)
            #pragma unroll
            for (int c = 0; c < 4; c++) acc[mt][nt][c] = 0.0f;

    // ldmatrix lane addressing (byte offsets within a stage)
    const uint32_t a_row = (uint32_t)(warp_m * 64 + ((lane >> 3) & 1) * 8 + (lane & 7));
    const uint32_t a_off0 = (a_row * LDH + ((lane >> 4) & 1) * 8) * 2u;
    const uint32_t b_row = (uint32_t)(warp_n * 32 + ((lane >> 4) & 1) * 8 + (lane & 7));
    const uint32_t b_off0 = (uint32_t)B_OFF_BYTES +
                            (b_row * LDH + ((lane >> 3) & 1) * 8) * 2u;

    uint32_t aF[2][4][4];   // [buf][mt][reg]
    uint32_t bF[2][2][4];   // [buf][pr][reg]: {b0,b1} of nt=2pr then 2pr+1

    auto prefetch = [&](int buf, uint32_t aS, uint32_t bS, int ks) {
        const uint32_t ao = aS + ks * 32;   // 16 fp16 = 32 B per k-step
        const uint32_t bo = bS + ks * 32;
        #pragma unroll
        for (int mt = 0; mt < 4; mt++)
            ldsm_x4(aF[buf][mt], ao + mt * (16 * LDH * 2));
        #pragma unroll
        for (int pr = 0; pr < 2; pr++)
            ldsm_x4(bF[buf][pr], bo + pr * (16 * LDH * 2));
    };
    auto do_mmas = [&](int buf) {
        #pragma unroll
        for (int mt = 0; mt < 4; mt++)
            #pragma unroll
            for (int nt = 0; nt < 4; nt++) {
                const uint32_t* bp = &bF[buf][nt >> 1][(nt & 1) * 2];
                asm volatile(
                    "mma.sync.aligned.m16n8k16.row.col.f32.f16.f16.f32 "
                    "{%0,%1,%2,%3}, {%4,%5,%6,%7}, {%8,%9}, {%0,%1,%2,%3};\n"
                    : "+f"(acc[mt][nt][0]), "+f"(acc[mt][nt][1]),
                      "+f"(acc[mt][nt][2]), "+f"(acc[mt][nt][3])
                    : "r"(aF[buf][mt][0]), "r"(aF[buf][mt][1]),
                      "r"(aF[buf][mt][2]), "r"(aF[buf][mt][3]),
                      "r"(bp[0]), "r"(bp[1]));
            }
    };

    // prologue: 2 stages in flight, stage 0 ready, ks0 fragments loaded
    issue_stage(0); cp_commit();
    issue_stage(1); cp_commit();
    cp_wait<NS - 2>();
    __syncthreads();
    prefetch(0, sbase + a_off0, sbase + b_off0, 0);

    for (int kc = 0; kc < 16; kc++) {
        const uint32_t stg = sbase + (uint32_t)((kc % NS) * STAGE_BYTES);
        const uint32_t aS = stg + a_off0;
        const uint32_t bS = stg + b_off0;

        if (kc + 2 < 16) issue_stage(kc + 2);
        cp_commit();                      // empty tail groups keep counts uniform

        #pragma unroll
        for (int ks = 0; ks < 3; ks++) {  // ks0..2: prefetch ks+1, then MMA ks
            prefetch((ks + 1) & 1, aS, bS, ks + 1);
            do_mmas(ks & 1);
        }

        if (kc < 15) {
            // barrier + next-stage ks0 ldmatrix hidden behind ks=3 MMAs below
            cp_wait<NS - 2>();
            __syncthreads();
            const uint32_t nstg = sbase + (uint32_t)(((kc + 1) % NS) * STAGE_BYTES);
            prefetch(0, nstg + a_off0, nstg + b_off0, 0);
        }
        do_mmas(1);                       // ks=3 (fragments loaded at ks==2)
    }

    // epilogue: y[b][i=nb][t][e]
    float* yb = y + ((size_t)b * 8 + nb) * 4096u * 128u;
    #pragma unroll
    for (int mt = 0; mt < 4; mt++) {
        const int row = t0 + warp_m * 64 + mt * 16 + (lane >> 2);
        #pragma unroll
        for (int nt = 0; nt < 4; nt++) {
            const int e = warp_n * 32 + nt * 8 + (lane & 3) * 2;
            *reinterpret_cast<float2*>(yb + (size_t)row * 128 + e) =
                make_float2(acc[mt][nt][0], acc[mt][nt][1]);
            *reinterpret_cast<float2*>(yb + (size_t)(row + 8) * 128 + e) =
                make_float2(acc[mt][nt][2], acc[mt][nt][3]);
        }
    }
}

extern "C" void kernel_launch(void* const* d_in, const int* in_sizes, int n_in,
                              void* d_out, int out_size) {
    const float* x    = (const float*)d_in[0];   // [8,8,4096,128] fp32
    const float* W    = (const float*)d_in[1];   // [8,128,128] fp32
    const float* beta = (const float*)d_in[2];   // [128] fp32
    float* y = (float*)d_out;                    // [8,8,4096,128] fp32
    (void)in_sizes; (void)n_in; (void)out_size;

    cudaFuncSetAttribute(octo_gemm_kernel,
                         cudaFuncAttributeMaxDynamicSharedMemorySize, SMEM_BYTES);

    conv_x_kernel<<<32768, 256>>>(x);
    prep_wf_kernel<<<dim3(32, 32), dim3(32, 32)>>>(W, beta);

    dim3 grid(8, 32, 8);   // n-tiles fastest: 8 CTAs share each x tile in L2
    octo_gemm_kernel<<<grid, 256, SMEM_BYTES>>>(y);
}